// round 7
// baseline (speedup 1.0000x reference)
#include <cuda_runtime.h>
#include <cstdint>
#include <cfloat>

#define NB 256
#define NQ 1000
#define NC 80
#define TOPK 300
#define NPAD 1024
#define T1 512
#define TILE_ROWS 128
#define T2 256

typedef unsigned long long ull;

// per-(batch,query) packed keys: [ordered score 32b | (1023-q) 10b | label 10b]
__device__ ull g_keys[NB * NQ];

__device__ __forceinline__ unsigned f2ord(float f) {
    unsigned u = __float_as_uint(f);
    return (u & 0x80000000u) ? ~u : (u | 0x80000000u);
}
__device__ __forceinline__ float ord2f(unsigned u) {
    return (u & 0x80000000u) ? __uint_as_float(u & 0x7FFFFFFFu)
                             : __uint_as_float(~u);
}
__device__ __forceinline__ void cswap(ull& a, ull& c, bool desc) {
    if (desc ? (a < c) : (a > c)) { ull t = a; a = c; c = t; }
}

// ---------------------------------------------------------------------------
// Kernel 1 (~5.2 TB/s): tile-streaming max/argmax via smem de-swizzle.
// 5 float4 LDGs/thread in flight, stride-81 smem layout (conflict-free),
// 4 threads/row reduce 80 elements with first-index tie-break.
// ---------------------------------------------------------------------------
__global__ __launch_bounds__(T1)
void score_kernel(const float* __restrict__ logits)
{
    __shared__ float sm[TILE_ROWS * 81];

    const int tid = threadIdx.x;
    const size_t f4base = (size_t)blockIdx.x * (TILE_ROWS * NC / 4);
    const float4* src = (const float4*)logits + f4base;

    float4 v[5];
    #pragma unroll
    for (int i = 0; i < 5; i++) v[i] = __ldcs(src + tid + T1 * i);

    #pragma unroll
    for (int i = 0; i < 5; i++) {
        int fl = (tid + T1 * i) * 4;
        int r  = fl / NC;
        int c  = fl - r * NC;
        float* d = &sm[r * 81 + c];
        d[0] = v[i].x; d[1] = v[i].y; d[2] = v[i].z; d[3] = v[i].w;
    }
    __syncthreads();

    const int r  = tid >> 2;
    const int qt = tid & 3;
    const float* row = &sm[r * 81 + qt * 20];
    float best = row[0]; int bi = 0;
    #pragma unroll
    for (int i = 1; i < 20; i++) {
        float x = row[i];
        if (x > best) { best = x; bi = i; }
    }
    bi += qt * 20;
    #pragma unroll
    for (int off = 2; off; off >>= 1) {
        float ov = __shfl_down_sync(0xffffffffu, best, off);
        int   oi = __shfl_down_sync(0xffffffffu, bi,  off);
        if (ov > best) { best = ov; bi = oi; }
    }

    if (qt == 0) {
        int g  = blockIdx.x * TILE_ROWS + r;
        int b  = g / NQ;
        int qq = g - b * NQ;
        float s  = 1.0f / (1.0f + expf(-best));
        float ms = (s > 0.05f) ? s : -1.0f;
        g_keys[g] = ((ull)f2ord(ms) << 32) | ((ull)(1023 - qq) << 10) | (unsigned)bi;
    }
}

// ---------------------------------------------------------------------------
// Kernel 2: REGISTER bitonic sort. 256 threads x 4 keys (idx = tid*4 + v).
//   j=1,2        : in-register compare-swap
//   j=4..64      : __shfl_xor exchange (lane xor j/4)
//   j=128,256,512: smem exchange (6 steps total), transposed conflict-free
// Keys are unique => min/max reproduces exact stable top_k order.
// ---------------------------------------------------------------------------
__global__ __launch_bounds__(T2)
void sort_emit_kernel(const float* __restrict__ pboxes,
                      const float* __restrict__ tsizes,
                      float* __restrict__ out)
{
    __shared__ ull sh[NPAD];

    const int b    = blockIdx.x;
    const int tid  = threadIdx.x;
    const int lane = tid & 31;

    // ---- load 4 keys per thread (16B-aligned vector loads where valid) ----
    ull v[4];
    if (tid < NQ / 4) {                       // tid < 250: fully in-range
        const ulonglong2* src = (const ulonglong2*)(g_keys + b * NQ + tid * 4);
        ulonglong2 x0 = src[0], x1 = src[1];
        v[0] = x0.x; v[1] = x0.y; v[2] = x1.x; v[3] = x1.y;
    } else {
        v[0] = v[1] = v[2] = v[3] = 0ULL;     // padding = minimal key
    }

    // ---- k = 2 (pair directions alternate inside the thread) ----
    cswap(v[0], v[1], true);
    cswap(v[2], v[3], false);

    // ---- k = 4 (whole thread is one block) ----
    {
        bool up = ((tid & 1) == 0);
        cswap(v[0], v[2], up); cswap(v[1], v[3], up);
        cswap(v[0], v[1], up); cswap(v[2], v[3], up);
    }

    // ---- k = 8 .. 1024 ----
    for (int k = 8; k <= NPAD; k <<= 1) {
        const bool up = (((tid << 2) & k) == 0);

        // cross-warp steps via smem (j >= 128)
        for (int j = k >> 1; j >= 128; j >>= 1) {
            int m = j >> 2;                   // partner tid xor m (32/64/128)
            #pragma unroll
            for (int t = 0; t < 4; t++) sh[t * T2 + tid] = v[t];
            __syncthreads();
            bool side = (tid & m) != 0;
            int ptid  = tid ^ m;
            #pragma unroll
            for (int t = 0; t < 4; t++) {
                ull p = sh[t * T2 + ptid];
                bool keepmax = up != side;
                v[t] = keepmax ? (v[t] > p ? v[t] : p)
                               : (v[t] < p ? v[t] : p);
            }
            __syncthreads();
        }

        // intra-warp steps via shfl (j = 4..64 -> lane xor 1..16)
        int jstart = (k >> 1) < 64 ? (k >> 1) : 64;
        for (int j = jstart; j >= 4; j >>= 1) {
            int m = j >> 2;
            bool side = (lane & m) != 0;
            bool keepmax = up != side;
            #pragma unroll
            for (int t = 0; t < 4; t++) {
                ull p = __shfl_xor_sync(0xffffffffu, v[t], m);
                v[t] = keepmax ? (v[t] > p ? v[t] : p)
                               : (v[t] < p ? v[t] : p);
            }
        }

        // intra-thread tail (j = 2, 1)
        cswap(v[0], v[2], up); cswap(v[1], v[3], up);
        cswap(v[0], v[1], up); cswap(v[2], v[3], up);
    }

    // ---- stage top-304 keys to smem for the emit gather ----
    if (tid < (TOPK + 3) / 4 + 1) {           // covers idx 0..303+
        #pragma unroll
        for (int t = 0; t < 4; t++) sh[tid * 4 + t] = v[t];
    }
    __syncthreads();

    // ---- emit top-300 ----
    const float img_h = tsizes[b * 2 + 0];
    const float img_w = tsizes[b * 2 + 1];
    for (int i = tid; i < TOPK; i += T2) {
        ull key     = sh[i];
        float s     = ord2f((unsigned)(key >> 32));
        int   q     = 1023 - (int)((key >> 10) & 0x3FFu);
        int   label = (int)(key & 0x3FFu);
        bool  valid = s > 0.05f;

        int o = b * TOPK + i;
        out[o]             = valid ? s : 0.0f;
        out[NB * TOPK + o] = valid ? (float)label : -1.0f;

        float4 rr = make_float4(0.f, 0.f, 0.f, 0.f);
        if (valid) {
            float4 pb = *(const float4*)(pboxes + ((size_t)b * NQ + q) * 4);
            rr.x = (pb.x - 0.5f * pb.z) * img_w;
            rr.y = (pb.y - 0.5f * pb.w) * img_h;
            rr.z = (pb.x + 0.5f * pb.z) * img_w;
            rr.w = (pb.y + 0.5f * pb.w) * img_h;
        }
        *(float4*)(out + 2 * NB * TOPK + (size_t)o * 4) = rr;
    }
}

extern "C" void kernel_launch(void* const* d_in, const int* in_sizes, int n_in,
                              void* d_out, int out_size) {
    const float* logits = (const float*)d_in[0];  // (256,1000,80)
    const float* boxes  = (const float*)d_in[1];  // (256,1000,4)
    const float* tsz    = (const float*)d_in[2];  // (256,2)
    float* out = (float*)d_out;

    score_kernel<<<NB * NQ / TILE_ROWS, T1>>>(logits);   // 625 blocks
    sort_emit_kernel<<<NB, T2>>>(boxes, tsz, out);       // 256 blocks
}